// round 7
// baseline (speedup 1.0000x reference)
#include <cuda_runtime.h>
#include <math_constants.h>

// Analytic collapse of the 18-qubit circuit (derivation in R1):
//   theta_{b,i} = (x_{b,i} - min(x)) / (max(x) - min(x)) * 2*pi - pi
//   <Z_i>_b = cos(a_i)cos(b_i)*cos(th_i) - sin(b_i)*sin(th_i)*cos(th_{i-1})*cos(th_{i+1})
//   out_b = sum_i head_w[i] * <Z_i>_b + head_b
// R7 (final): single-warp CTA per batch row; redundant per-CTA global min/max
// (input is 4.6KB, L2-resident); MUFU trig; MUFU divide; warp-synchronous
// throughout. Measured at the single-launch overhead floor (~6.6us wall,
// ~4.3us device, all pipes <0.5%).

#define NW 18
#define NB 64
#define NELEM (NB * NW)   // 1152
#define NVEC  (NELEM / 4) // 288 = 32 * 9

__global__ void __launch_bounds__(32, 1)
qcircuit_analytic_kernel(const float* __restrict__ sb,
                         const float* __restrict__ params,
                         const float* __restrict__ hw,
                         const float* __restrict__ hb,
                         float* __restrict__ out) {
    const int lane = threadIdx.x;
    const int row  = blockIdx.x;

    // ---- per-row element load first: latency overlaps everything below ----
    const int idx = row * NW + ((lane < NW) ? lane : 0);
    float x = sb[idx];

    // ---- full min/max over all 1152 inputs: 9 float4 per lane (MLP=9) ----
    const float4* sb4 = (const float4*)sb;
    float4 v0 = sb4[lane];
    float4 v1 = sb4[lane + 32];
    float4 v2 = sb4[lane + 64];
    float4 v3 = sb4[lane + 96];
    float4 v4 = sb4[lane + 128];
    float4 v5 = sb4[lane + 160];
    float4 v6 = sb4[lane + 192];
    float4 v7 = sb4[lane + 224];
    float4 v8 = sb4[lane + 256];

    // ---- per-wire constants on lanes < NW (overlaps load latency) ----
    float cA = 0.0f, sB = 0.0f, wgt = 0.0f, bias = 0.0f;
    if (lane < NW) {
        float alpha = params[lane * 3 + 0];
        float beta  = params[lane * 3 + 1];
        cA  = __cosf(alpha) * __cosf(beta);
        sB  = __sinf(beta);
        wgt = hw[lane];
    }
    if (lane == 0) bias = hb[0];

    // local min/max tree (balanced, depth ~6)
    float a0 = fminf(fminf(v0.x, v0.y), fminf(v0.z, v0.w));
    float a1 = fminf(fminf(v1.x, v1.y), fminf(v1.z, v1.w));
    float a2 = fminf(fminf(v2.x, v2.y), fminf(v2.z, v2.w));
    float a3 = fminf(fminf(v3.x, v3.y), fminf(v3.z, v3.w));
    float a4 = fminf(fminf(v4.x, v4.y), fminf(v4.z, v4.w));
    float a5 = fminf(fminf(v5.x, v5.y), fminf(v5.z, v5.w));
    float a6 = fminf(fminf(v6.x, v6.y), fminf(v6.z, v6.w));
    float a7 = fminf(fminf(v7.x, v7.y), fminf(v7.z, v7.w));
    float a8 = fminf(fminf(v8.x, v8.y), fminf(v8.z, v8.w));
    float mn = fminf(fminf(fminf(a0, a1), fminf(a2, a3)),
                     fminf(fminf(a4, a5), fminf(a6, fminf(a7, a8))));
    float b0 = fmaxf(fmaxf(v0.x, v0.y), fmaxf(v0.z, v0.w));
    float b1 = fmaxf(fmaxf(v1.x, v1.y), fmaxf(v1.z, v1.w));
    float b2 = fmaxf(fmaxf(v2.x, v2.y), fmaxf(v2.z, v2.w));
    float b3 = fmaxf(fmaxf(v3.x, v3.y), fmaxf(v3.z, v3.w));
    float b4 = fmaxf(fmaxf(v4.x, v4.y), fmaxf(v4.z, v4.w));
    float b5 = fmaxf(fmaxf(v5.x, v5.y), fmaxf(v5.z, v5.w));
    float b6 = fmaxf(fmaxf(v6.x, v6.y), fmaxf(v6.z, v6.w));
    float b7 = fmaxf(fmaxf(v7.x, v7.y), fmaxf(v7.z, v7.w));
    float b8 = fmaxf(fmaxf(v8.x, v8.y), fmaxf(v8.z, v8.w));
    float mx = fmaxf(fmaxf(fmaxf(b0, b1), fmaxf(b2, b3)),
                     fmaxf(fmaxf(b4, b5), fmaxf(b6, fmaxf(b7, b8))));

    // ---- warp min/max reduce: two independent SHFL chains, explicitly
    //      interleaved so the 26-cycle SHFL latencies overlap ----
    float tmn, tmx;
#pragma unroll
    for (int s = 16; s > 0; s >>= 1) {
        tmn = __shfl_xor_sync(0xFFFFFFFFu, mn, s);
        tmx = __shfl_xor_sync(0xFFFFFFFFu, mx, s);
        mn = fminf(mn, tmn);
        mx = fmaxf(mx, tmx);
    }

    // scale via MUFU reciprocal (well within 1e-3 tolerance)
    const float scale = __fdividef(2.0f * CUDART_PI_F, mx - mn);
    float theta = fmaf(x - mn, scale, -CUDART_PI_F);
    float sz, cz;
    __sincosf(theta, &sz, &cz);

    float zl = __shfl_up_sync(0xFFFFFFFFu, cz, 1);    // cz[i-1]
    float zr = __shfl_down_sync(0xFFFFFFFFu, cz, 1);  // cz[i+1]
    if (lane == 0)      zl = 1.0f;
    if (lane == NW - 1) zr = 1.0f;

    float term = wgt * fmaf(cA, cz, -sB * sz * zl * zr) + bias;  // wgt=0 on lanes>=NW

#pragma unroll
    for (int s = 16; s > 0; s >>= 1)
        term += __shfl_xor_sync(0xFFFFFFFFu, term, s);

    if (lane == 0) out[row] = term;
}

extern "C" void kernel_launch(void* const* d_in, const int* in_sizes, int n_in,
                              void* d_out, int out_size) {
    const float* state_batch = (const float*)d_in[0]; // (64, 18)
    const float* params      = (const float*)d_in[1]; // (18, 3)
    const float* head_w      = (const float*)d_in[2]; // (1, 18)
    const float* head_b      = (const float*)d_in[3]; // (1,)
    float* out = (float*)d_out;                       // (64,)

    qcircuit_analytic_kernel<<<NB, 32>>>(state_batch, params, head_w, head_b, out);
}

// round 8
// speedup vs baseline: 1.0299x; 1.0299x over previous
#include <cuda_runtime.h>
#include <math_constants.h>

// Analytic collapse of the 18-qubit circuit (derivation in R1):
//   theta_{b,i} = (x_{b,i} - min(x)) / (max(x) - min(x)) * 2*pi - pi
//   <Z_i>_b = cos(a_i)cos(b_i)*cos(th_i) - sin(b_i)*sin(th_i)*cos(th_{i-1})*cos(th_{i+1})
//   out_b = sum_i head_w[i] * <Z_i>_b + head_b
// R8: integer redux.sync (sm_80+; the f32 variants don't exist on sm_103a)
// replaces all three SHFL reduction trees:
//   - min/max via order-preserving float<->u32 bijection + redux.min/max.u32
//   - final dot-product sum via 2^-24 fixed-point + redux.add.s32 (error ~2e-6,
//     deterministic, three orders under the 1e-3 gate)
// Single-warp CTA per batch row; redundant per-CTA global min/max (4.6KB input).

#define NW 18
#define NB 64
#define NELEM (NB * NW)   // 1152
#define NVEC  (NELEM / 4) // 288 = 32 * 9

#define FIXED_SCALE 16777216.0f          // 2^24
#define FIXED_INV   (1.0f / 16777216.0f)

// order-preserving float -> u32 (total order; inputs are finite)
__device__ __forceinline__ unsigned f2ord(float f) {
    unsigned u = __float_as_uint(f);
    return (u & 0x80000000u) ? ~u : (u | 0x80000000u);
}
__device__ __forceinline__ float ord2f(unsigned u) {
    return (u & 0x80000000u) ? __uint_as_float(u & 0x7FFFFFFFu)
                             : __uint_as_float(~u);
}

__device__ __forceinline__ unsigned redux_min_u32(unsigned v) {
    unsigned r;
    asm("redux.sync.min.u32 %0, %1, 0xffffffff;" : "=r"(r) : "r"(v));
    return r;
}
__device__ __forceinline__ unsigned redux_max_u32(unsigned v) {
    unsigned r;
    asm("redux.sync.max.u32 %0, %1, 0xffffffff;" : "=r"(r) : "r"(v));
    return r;
}
__device__ __forceinline__ int redux_add_s32(int v) {
    int r;
    asm("redux.sync.add.s32 %0, %1, 0xffffffff;" : "=r"(r) : "r"(v));
    return r;
}

__global__ void __launch_bounds__(32, 1)
qcircuit_analytic_kernel(const float* __restrict__ sb,
                         const float* __restrict__ params,
                         const float* __restrict__ hw,
                         const float* __restrict__ hb,
                         float* __restrict__ out) {
    const int lane = threadIdx.x;
    const int row  = blockIdx.x;

    // ---- per-row element load first: latency overlaps everything below ----
    const int idx = row * NW + ((lane < NW) ? lane : 0);
    float x = sb[idx];

    // ---- full min/max over all 1152 inputs: 9 float4 per lane (MLP=9) ----
    const float4* sb4 = (const float4*)sb;
    float4 v0 = sb4[lane];
    float4 v1 = sb4[lane + 32];
    float4 v2 = sb4[lane + 64];
    float4 v3 = sb4[lane + 96];
    float4 v4 = sb4[lane + 128];
    float4 v5 = sb4[lane + 160];
    float4 v6 = sb4[lane + 192];
    float4 v7 = sb4[lane + 224];
    float4 v8 = sb4[lane + 256];

    // ---- per-wire constants on lanes < NW (overlaps load latency) ----
    float cA = 0.0f, sB = 0.0f, wgt = 0.0f, bias = 0.0f;
    if (lane < NW) {
        float alpha = params[lane * 3 + 0];
        float beta  = params[lane * 3 + 1];
        cA  = __cosf(alpha) * __cosf(beta);
        sB  = __sinf(beta);
        wgt = hw[lane];
    }
    if (lane == 0) bias = hb[0];

    // local min/max tree (balanced, depth ~6)
    float a0 = fminf(fminf(v0.x, v0.y), fminf(v0.z, v0.w));
    float a1 = fminf(fminf(v1.x, v1.y), fminf(v1.z, v1.w));
    float a2 = fminf(fminf(v2.x, v2.y), fminf(v2.z, v2.w));
    float a3 = fminf(fminf(v3.x, v3.y), fminf(v3.z, v3.w));
    float a4 = fminf(fminf(v4.x, v4.y), fminf(v4.z, v4.w));
    float a5 = fminf(fminf(v5.x, v5.y), fminf(v5.z, v5.w));
    float a6 = fminf(fminf(v6.x, v6.y), fminf(v6.z, v6.w));
    float a7 = fminf(fminf(v7.x, v7.y), fminf(v7.z, v7.w));
    float a8 = fminf(fminf(v8.x, v8.y), fminf(v8.z, v8.w));
    float mnl = fminf(fminf(fminf(a0, a1), fminf(a2, a3)),
                      fminf(fminf(a4, a5), fminf(a6, fminf(a7, a8))));
    float b0 = fmaxf(fmaxf(v0.x, v0.y), fmaxf(v0.z, v0.w));
    float b1 = fmaxf(fmaxf(v1.x, v1.y), fmaxf(v1.z, v1.w));
    float b2 = fmaxf(fmaxf(v2.x, v2.y), fmaxf(v2.z, v2.w));
    float b3 = fmaxf(fmaxf(v3.x, v3.y), fmaxf(v3.z, v3.w));
    float b4 = fmaxf(fmaxf(v4.x, v4.y), fmaxf(v4.z, v4.w));
    float b5 = fmaxf(fmaxf(v5.x, v5.y), fmaxf(v5.z, v5.w));
    float b6 = fmaxf(fmaxf(v6.x, v6.y), fmaxf(v6.z, v6.w));
    float b7 = fmaxf(fmaxf(v7.x, v7.y), fmaxf(v7.z, v7.w));
    float b8 = fmaxf(fmaxf(v8.x, v8.y), fmaxf(v8.z, v8.w));
    float mxl = fmaxf(fmaxf(fmaxf(b0, b1), fmaxf(b2, b3)),
                      fmaxf(fmaxf(b4, b5), fmaxf(b6, fmaxf(b7, b8))));

    // ---- warp min/max: single REDUX each via order-preserving u32 map ----
    float mn = ord2f(redux_min_u32(f2ord(mnl)));
    float mx = ord2f(redux_max_u32(f2ord(mxl)));

    // scale via MUFU reciprocal (well within 1e-3 tolerance)
    const float scale = __fdividef(2.0f * CUDART_PI_F, mx - mn);
    float theta = fmaf(x - mn, scale, -CUDART_PI_F);
    float sz, cz;
    __sincosf(theta, &sz, &cz);

    float zl = __shfl_up_sync(0xFFFFFFFFu, cz, 1);    // cz[i-1]
    float zr = __shfl_down_sync(0xFFFFFFFFu, cz, 1);  // cz[i+1]
    if (lane == 0)      zl = 1.0f;
    if (lane == NW - 1) zr = 1.0f;

    float term = wgt * fmaf(cA, cz, -sB * sz * zl * zr) + bias;  // wgt=0 on lanes>=NW

    // ---- final dot-product sum: fixed-point + single integer REDUX ----
    int ti   = __float2int_rn(term * FIXED_SCALE);   // |term| <~ 5 -> fits s32
    int tsum = redux_add_s32(ti);

    if (lane == 0) out[row] = (float)tsum * FIXED_INV;
}

extern "C" void kernel_launch(void* const* d_in, const int* in_sizes, int n_in,
                              void* d_out, int out_size) {
    const float* state_batch = (const float*)d_in[0]; // (64, 18)
    const float* params      = (const float*)d_in[1]; // (18, 3)
    const float* head_w      = (const float*)d_in[2]; // (1, 18)
    const float* head_b      = (const float*)d_in[3]; // (1,)
    float* out = (float*)d_out;                       // (64,)

    qcircuit_analytic_kernel<<<NB, 32>>>(state_batch, params, head_w, head_b, out);
}